// round 12
// baseline (speedup 1.0000x reference)
#include <cuda_runtime.h>
#include <cuda_bf16.h>
#include <cstdint>

#define NROWS    16384
#define NCODES   8192
#define DIMD     256
#define HWQ      1024
#define ZQ_ELEMS 4194304
#define MARGIN   5e-4f
#define CAP      512

#define SZ  (127.0f / 6.5f)
#define SE  (127.0f * 8192.0f)
#define C2  (2.0f / (SZ * SE))

// Scratch (device globals; no allocations allowed)
__device__ __align__(16) signed char g_zq[NROWS * DIMD];       // 4 MB int8 (screen)
__device__ __align__(16) signed char g_cbq[NCODES * DIMD];     // 2 MB int8 (screen)
__device__ __align__(16) float       g_zt[NROWS * DIMD];       // 16 MB exact fp32
__device__ float g_bsq[NCODES];
__device__ uint32_t g_rowmax[NROWS];
__device__ int      g_cnt[NROWS];
__device__ __align__(16) uint2 g_cand[(size_t)NROWS * CAP];    // 64 MB
__device__ int   g_idx[NROWS];
__device__ float g_loss;
__device__ int   g_blocks_done;

// ---------------- helpers ----------------
__device__ __forceinline__ uint32_t smem_u32(const void* p) {
    uint32_t a;
    asm("{ .reg .u64 t; cvta.to.shared.u64 t, %1; cvt.u32.u64 %0, t; }" : "=r"(a) : "l"(p));
    return a;
}
__device__ __forceinline__ uint32_t swz(uint32_t off) { return off ^ ((off >> 3) & 0x70); }
__device__ __forceinline__ uint32_t f2u(float f) {
    uint32_t b = __float_as_uint(f);
    return (b >> 31) ? ~b : (b | 0x80000000u);
}
__device__ __forceinline__ float u2f(uint32_t u) {
    return __uint_as_float((u >> 31) ? (u & 0x7FFFFFFFu) : ~u);
}
__device__ __forceinline__ int q8(float v, float s) {
    return __float2int_rn(fminf(fmaxf(v * s, -127.0f), 127.0f));
}

#define CP_ASYNC16(dst, src) \
    asm volatile("cp.async.cg.shared.global [%0], [%1], 16;" :: "r"(dst), "l"(src) : "memory")
#define CP_COMMIT() asm volatile("cp.async.commit_group;" ::: "memory")

#define LDSM_X4(r0, r1, r2, r3, addr) \
    asm volatile("ldmatrix.sync.aligned.m8n8.x4.shared.b16 {%0,%1,%2,%3}, [%4];" \
        : "=r"(r0), "=r"(r1), "=r"(r2), "=r"(r3) : "r"(addr))

#define MMA16832(d, a, b0, b1) \
    asm volatile("mma.sync.aligned.m16n8k32.row.col.s32.s8.s8.s32 " \
        "{%0,%1,%2,%3}, {%4,%5,%6,%7}, {%8,%9}, {%0,%1,%2,%3};" \
        : "+r"((d)[0]), "+r"((d)[1]), "+r"((d)[2]), "+r"((d)[3]) \
        : "r"((a)[0]), "r"((a)[1]), "r"((a)[2]), "r"((a)[3]), "r"(b0), "r"(b1))

// ---------------- prep (single launch): z transpose+int8+init | codebook int8+bsq ----------------
__global__ void k_prep(const float* __restrict__ z, const float* __restrict__ cb) {
    __shared__ float tile[32][33];
    const int blk = blockIdx.x;
    const int t = threadIdx.x;

    if (blk < 4096) {
        int bx = blk & 31, by = (blk >> 5) & 7, bz = blk >> 8;
        int tx = t & 31, ty = t >> 5;
        int d0 = by * 32, p0 = bx * 32;
        const float* src = z + ((size_t)(bz * DIMD + d0) << 10) + p0;
#pragma unroll
        for (int i = ty; i < 32; i += 8)
            tile[i][tx] = src[((size_t)i << 10) + tx];

        {
            int gi = blk * 256 + t;
            if (gi < NROWS) { g_cnt[gi] = 0; g_rowmax[gi] = f2u(-1e30f); }
            if (gi == 0) { g_loss = 0.0f; g_blocks_done = 0; }
        }
        __syncthreads();

        float* dst = g_zt + (size_t)(bz * HWQ + p0) * DIMD + d0;
        signed char* dq = g_zq + (size_t)(bz * HWQ + p0) * DIMD + d0;
#pragma unroll
        for (int i = ty; i < 32; i += 8) {
            float v = tile[tx][i];
            dst[(size_t)i * DIMD + tx] = v;
            dq[(size_t)i * DIMD + tx] = (signed char)q8(v, SZ);
        }
    } else {
        int w = (blk - 4096) * 8 + (t >> 5);
        int lane = t & 31;
        if (w < NCODES) {
            const float4* row = reinterpret_cast<const float4*>(cb + (size_t)w * DIMD);
            float4 v0 = row[lane * 2], v1 = row[lane * 2 + 1];

            int q0 = q8(v0.x, SE) & 0xFF, q1 = q8(v0.y, SE) & 0xFF;
            int q2 = q8(v0.z, SE) & 0xFF, q3 = q8(v0.w, SE) & 0xFF;
            int q4 = q8(v1.x, SE) & 0xFF, q5 = q8(v1.y, SE) & 0xFF;
            int q6 = q8(v1.z, SE) & 0xFF, q7 = q8(v1.w, SE) & 0xFF;
            uint2 pk;
            pk.x = (unsigned)(q0 | (q1 << 8) | (q2 << 16) | (q3 << 24));
            pk.y = (unsigned)(q4 | (q5 << 8) | (q6 << 16) | (q7 << 24));
            *reinterpret_cast<uint2*>(g_cbq + (size_t)w * DIMD + lane * 8) = pk;

            float s = 0.0f;
            s = fmaf(v0.x, v0.x, s); s = fmaf(v0.y, v0.y, s);
            s = fmaf(v0.z, v0.z, s); s = fmaf(v0.w, v0.w, s);
            s = fmaf(v1.x, v1.x, s); s = fmaf(v1.y, v1.y, s);
            s = fmaf(v1.z, v1.z, s); s = fmaf(v1.w, v1.w, s);
#pragma unroll
            for (int off = 16; off; off >>= 1)
                s += __shfl_xor_sync(0xFFFFFFFFu, s, off);
            if (lane == 0) g_bsq[w] = s;
        }
    }
}

// ---------------- int8 IMMA GEMM 128x128 + fused argmax/candidate epilogue ----------------
// Byte-layout identical to the proven bf16 kernel: each "b16" = 2 int8 along k.
// K=256 int8 = 2 chunks of 128 bytes/row; same swizzle/ldmatrix addressing.
__global__ void __launch_bounds__(256, 2) k_gemm() {
    extern __shared__ __align__(1024) unsigned char smem[];
    const uint32_t sA = smem_u32(smem);        // 2 x 16KB
    const uint32_t sB = sA + 32768;            // 2 x 16KB
    __shared__ uint32_t s_rmax[128];

    const int t = threadIdx.x;
    const int lane = t & 31, wid = t >> 5;
    const int wy = wid >> 2, wx = wid & 3;
    const int m0 = blockIdx.y * 128, n0 = blockIdx.x * 128;

    const char* gA = (const char*)(g_zq  + (size_t)m0 * DIMD);
    const char* gB = (const char*)(g_cbq + (size_t)n0 * DIMD);

    const int ld_row[4] = { (t + 0) >> 3, (t + 256) >> 3, (t + 512) >> 3, (t + 768) >> 3 };
    const int ld_seg = t & 7;

    int acc[4][4][4];
#pragma unroll
    for (int a = 0; a < 4; a++)
#pragma unroll
        for (int b = 0; b < 4; b++)
#pragma unroll
            for (int c = 0; c < 4; c++) acc[a][b][c] = 0;

#define ISSUE(c) do {                                                           \
    uint32_t dA = sA + ((c) & 1) * 16384;                                       \
    uint32_t dB = sB + ((c) & 1) * 16384;                                       \
    _Pragma("unroll")                                                           \
    for (int i = 0; i < 4; i++) {                                               \
        uint32_t off = swz((uint32_t)(ld_row[i] * 128 + ld_seg * 16));          \
        size_t go = (size_t)ld_row[i] * 256 + (c) * 128 + ld_seg * 16;          \
        CP_ASYNC16(dA + off, gA + go);                                          \
        CP_ASYNC16(dB + off, gB + go);                                          \
    }                                                                           \
    CP_COMMIT();                                                                \
} while (0)

    ISSUE(0);
    ISSUE(1);

    const int g = lane >> 3, r = lane & 7;
    const int aRow = wy * 64 + (g & 1) * 8 + r;
    const int bRow = wx * 32 + (g & 1) * 8 + r;
    const int kCol = (g >> 1) * 8;

#pragma unroll 1
    for (int c = 0; c < 2; c++) {
        if (c == 0) asm volatile("cp.async.wait_group 1;" ::: "memory");
        else        asm volatile("cp.async.wait_group 0;" ::: "memory");
        __syncthreads();

        const uint32_t bA = sA + c * 16384;
        const uint32_t bB = sB + c * 16384;
#pragma unroll
        for (int ks = 0; ks < 4; ks++) {
            uint32_t af[4][4], bfr[2][4];
#pragma unroll
            for (int mt = 0; mt < 4; mt++) {
                uint32_t off = (uint32_t)((aRow + mt * 16) * 128 + (kCol + ks * 16) * 2);
                LDSM_X4(af[mt][0], af[mt][1], af[mt][2], af[mt][3], bA + swz(off));
            }
#pragma unroll
            for (int bt = 0; bt < 2; bt++) {
                uint32_t off = (uint32_t)((bRow + bt * 16) * 128 + (kCol + ks * 16) * 2);
                LDSM_X4(bfr[bt][0], bfr[bt][1], bfr[bt][2], bfr[bt][3], bB + swz(off));
            }
#pragma unroll
            for (int mt = 0; mt < 4; mt++)
#pragma unroll
                for (int bt = 0; bt < 2; bt++) {
                    MMA16832(acc[mt][bt * 2 + 0], af[mt], bfr[bt][0], bfr[bt][2]);
                    MMA16832(acc[mt][bt * 2 + 1], af[mt], bfr[bt][1], bfr[bt][3]);
                }
        }
    }
#undef ISSUE

    // ---- fused epilogue: score = C2*idot - bsq ----
    const int cRow = lane >> 2, cCol = (lane & 3) * 2;
    float bq[8];
#pragma unroll
    for (int nn = 0; nn < 4; nn++) {
        int col = n0 + wx * 32 + nn * 8 + cCol;
        bq[nn * 2 + 0] = g_bsq[col];
        bq[nn * 2 + 1] = g_bsq[col + 1];
    }

    if (t < 128) s_rmax[t] = 0u;
    __syncthreads();

#pragma unroll
    for (int mt = 0; mt < 4; mt++) {
#pragma unroll
        for (int h = 0; h < 2; h++) {
            float m = -1e30f;
#pragma unroll
            for (int nn = 0; nn < 4; nn++) {
                float s0 = fmaf(C2, __int2float_rn(acc[mt][nn][h * 2 + 0]), -bq[nn * 2 + 0]);
                float s1 = fmaf(C2, __int2float_rn(acc[mt][nn][h * 2 + 1]), -bq[nn * 2 + 1]);
                m = fmaxf(m, fmaxf(s0, s1));
            }
            atomicMax(&s_rmax[wy * 64 + mt * 16 + h * 8 + cRow], f2u(m));
        }
    }
    __syncthreads();
    if (t < 128) atomicMax(&g_rowmax[m0 + t], s_rmax[t]);

#pragma unroll
    for (int mt = 0; mt < 4; mt++) {
#pragma unroll
        for (int h = 0; h < 2; h++) {
            int rl = wy * 64 + mt * 16 + h * 8 + cRow;
            int row = m0 + rl;
            uint32_t gm = *(volatile uint32_t*)&g_rowmax[row];
            uint32_t tu = max(gm, s_rmax[rl]);
            float thr = u2f(tu) - MARGIN;
#pragma unroll
            for (int nn = 0; nn < 4; nn++) {
#pragma unroll
                for (int q = 0; q < 2; q++) {
                    float s = fmaf(C2, __int2float_rn(acc[mt][nn][h * 2 + q]), -bq[nn * 2 + q]);
                    if (s >= thr) {
                        int pos = atomicAdd(&g_cnt[row], 1);
                        if (pos < CAP)
                            g_cand[(size_t)row * CAP + pos] =
                                make_uint2((unsigned)(n0 + wx * 32 + nn * 8 + cCol + q),
                                           __float_as_uint(s));
                    }
                }
            }
        }
    }
}

// ---------------- rescue: filter by final max, exact fp32 rescore ----------------
__global__ void __launch_bounds__(256) k_rescue(const float* __restrict__ cb,
                                                float* __restrict__ out, int out_size) {
    const int w = threadIdx.x >> 5, lane = threadIdx.x & 31;
    const int row = blockIdx.x * 8 + w;

    const float thr = u2f(g_rowmax[row]) - MARGIN;
    const int cnt = g_cnt[row];

    const float4* zr = reinterpret_cast<const float4*>(g_zt + (size_t)row * DIMD);
    float4 z0 = zr[lane * 2], z1 = zr[lane * 2 + 1];
    float a = 0.0f;
    a = fmaf(z0.x, z0.x, a); a = fmaf(z0.y, z0.y, a);
    a = fmaf(z0.z, z0.z, a); a = fmaf(z0.w, z0.w, a);
    a = fmaf(z1.x, z1.x, a); a = fmaf(z1.y, z1.y, a);
    a = fmaf(z1.z, z1.z, a); a = fmaf(z1.w, z1.w, a);
#pragma unroll
    for (int off = 16; off; off >>= 1)
        a += __shfl_xor_sync(0xFFFFFFFFu, a, off);

    unsigned long long best = ~0ULL;
    if (cnt <= CAP) {
        for (int i = 0; i < cnt; i++) {
            uint2 e = g_cand[(size_t)row * CAP + i];
            if (__uint_as_float(e.y) < thr) continue;
            int k = (int)e.x;
            const float4* er = reinterpret_cast<const float4*>(cb + (size_t)k * DIMD);
            float4 e0 = er[lane * 2], e1 = er[lane * 2 + 1];
            float dot = 0.0f;
            dot = fmaf(z0.x, e0.x, dot); dot = fmaf(z0.y, e0.y, dot);
            dot = fmaf(z0.z, e0.z, dot); dot = fmaf(z0.w, e0.w, dot);
            dot = fmaf(z1.x, e1.x, dot); dot = fmaf(z1.y, e1.y, dot);
            dot = fmaf(z1.z, e1.z, dot); dot = fmaf(z1.w, e1.w, dot);
#pragma unroll
            for (int off = 16; off; off >>= 1)
                dot += __shfl_xor_sync(0xFFFFFFFFu, dot, off);
            float dist = __fadd_rn(__fadd_rn(a, g_bsq[k]), -2.0f * dot);
            unsigned long long key = ((unsigned long long)__float_as_uint(dist) << 32) | (unsigned)k;
            if (key < best) best = key;
        }
    } else {
        for (int k = 0; k < NCODES; k++) {
            const float4* er = reinterpret_cast<const float4*>(cb + (size_t)k * DIMD);
            float4 e0 = er[lane * 2], e1 = er[lane * 2 + 1];
            float dot = 0.0f;
            dot = fmaf(z0.x, e0.x, dot); dot = fmaf(z0.y, e0.y, dot);
            dot = fmaf(z0.z, e0.z, dot); dot = fmaf(z0.w, e0.w, dot);
            dot = fmaf(z1.x, e1.x, dot); dot = fmaf(z1.y, e1.y, dot);
            dot = fmaf(z1.z, e1.z, dot); dot = fmaf(z1.w, e1.w, dot);
#pragma unroll
            for (int off = 16; off; off >>= 1)
                dot += __shfl_xor_sync(0xFFFFFFFFu, dot, off);
            float dist = __fadd_rn(__fadd_rn(a, g_bsq[k]), -2.0f * dot);
            unsigned long long key = ((unsigned long long)__float_as_uint(dist) << 32) | (unsigned)k;
            if (key < best) best = key;
        }
    }
    if (lane == 0) {
        int idx = (int)(best & 0xFFFFFFFFu);
        g_idx[row] = idx;
        if (out_size >= ZQ_ELEMS + NROWS) out[ZQ_ELEMS + row] = (float)idx;
    }
}

// ---------------- output + fused loss: smem-transposed, fully coalesced ----------------
__global__ void __launch_bounds__(256) k_output(const float* __restrict__ cb,
                                                float* __restrict__ out, int out_size) {
    __shared__ float tile[256][33];
    __shared__ float warpsum[8];

    const int t = threadIdx.x, lane = t & 31, w = t >> 5;
    const int n0 = blockIdx.x * 32;
    const int b = n0 >> 10, p0 = n0 & 1023;

    float dsq = 0.0f;
#pragma unroll
    for (int it = 0; it < 4; it++) {
        int pl = it * 8 + w;
        int n = n0 + pl;
        int idx = g_idx[n];
        const float* er = cb   + (size_t)idx * DIMD;
        const float* zr = g_zt + (size_t)n   * DIMD;
#pragma unroll
        for (int j = 0; j < 8; j++) {
            int d = lane + 32 * j;
            float zv = zr[d];
            float e  = er[d];
            float f  = __fadd_rn(e, -zv);
            tile[d][pl] = __fadd_rn(zv, f);
            dsq = fmaf(f, f, dsq);
        }
    }
    __syncthreads();

    const int dr = t >> 3, pq = (t & 7) * 4;
#pragma unroll
    for (int g8 = 0; g8 < 8; g8++) {
        int d = g8 * 32 + dr;
        float4 o;
        o.x = tile[d][pq + 0];
        o.y = tile[d][pq + 1];
        o.z = tile[d][pq + 2];
        o.w = tile[d][pq + 3];
        size_t i = (size_t)b * DIMD * HWQ + (size_t)d * HWQ + p0 + pq;
        if (i + 3 < (size_t)out_size) {
            *reinterpret_cast<float4*>(out + i) = o;
        } else {
            if (i + 0 < (size_t)out_size) out[i + 0] = o.x;
            if (i + 1 < (size_t)out_size) out[i + 1] = o.y;
            if (i + 2 < (size_t)out_size) out[i + 2] = o.z;
            if (i + 3 < (size_t)out_size) out[i + 3] = o.w;
        }
    }

#pragma unroll
    for (int off = 16; off; off >>= 1)
        dsq += __shfl_xor_sync(0xFFFFFFFFu, dsq, off);
    if (lane == 0) warpsum[w] = dsq;
    __syncthreads();
    if (t == 0) {
        float s = 0.0f;
#pragma unroll
        for (int q = 0; q < 8; q++) s += warpsum[q];
        atomicAdd(&g_loss, s);
        __threadfence();
        int done = atomicAdd(&g_blocks_done, 1);
        if (done == (int)gridDim.x - 1) {
            g_blocks_done = 0;
            if (out_size >= ZQ_ELEMS + NROWS + 1) {
                float mean = g_loss / (float)ZQ_ELEMS;
                out[ZQ_ELEMS + NROWS] = 0.25f * mean;
            }
        }
    }
}

extern "C" void kernel_launch(void* const* d_in, const int* in_sizes, int n_in,
                              void* d_out, int out_size) {
    const float* z;
    const float* cb;
    if (n_in >= 2 && in_sizes[0] == ZQ_ELEMS) {
        z = (const float*)d_in[0]; cb = (const float*)d_in[1];
    } else {
        z = (const float*)d_in[1]; cb = (const float*)d_in[0];
    }
    float* out = (float*)d_out;

    cudaFuncSetAttribute(k_gemm, cudaFuncAttributeMaxDynamicSharedMemorySize, 65536);

    k_prep<<<4096 + NCODES / 8, 256>>>(z, cb);

    dim3 grid(NCODES / 128, NROWS / 128);  // (64, 128)
    k_gemm<<<grid, 256, 65536>>>();

    k_rescue<<<NROWS / 8, 256>>>(cb, out, out_size);
    k_output<<<NROWS / 32, 256>>>(cb, out, out_size);
}

// round 13
// speedup vs baseline: 1.9155x; 1.9155x over previous
#include <cuda_runtime.h>
#include <cuda_bf16.h>
#include <cstdint>

#define NROWS    16384
#define NCODES   8192
#define DIMD     256
#define HWQ      1024
#define ZQ_ELEMS 4194304
#define MARGIN   2e-4f
#define CAP      512

// Scratch (device globals; no allocations allowed)
__device__ __align__(16) __nv_bfloat16 g_zbf[NROWS * DIMD];    // 8 MB
__device__ __align__(16) __nv_bfloat16 g_cbbf[NCODES * DIMD];  // 4 MB
__device__ __align__(16) float         g_zt[NROWS * DIMD];     // 16 MB exact fp32
__device__ float g_bsq[NCODES];
__device__ uint32_t g_rowmax[NROWS];
__device__ int      g_cnt[NROWS];
__device__ __align__(16) uint2 g_cand[(size_t)NROWS * CAP];    // 64 MB
__device__ int   g_idx[NROWS];
__device__ float g_loss;
__device__ int   g_blocks_done;

// ---------------- helpers ----------------
__device__ __forceinline__ uint32_t smem_u32(const void* p) {
    uint32_t a;
    asm("{ .reg .u64 t; cvta.to.shared.u64 t, %1; cvt.u32.u64 %0, t; }" : "=r"(a) : "l"(p));
    return a;
}
__device__ __forceinline__ uint32_t swz(uint32_t off) { return off ^ ((off >> 3) & 0x70); }
__device__ __forceinline__ uint32_t f2u(float f) {
    uint32_t b = __float_as_uint(f);
    return (b >> 31) ? ~b : (b | 0x80000000u);
}
__device__ __forceinline__ float u2f(uint32_t u) {
    return __uint_as_float((u >> 31) ? (u & 0x7FFFFFFFu) : ~u);
}

#define CP_ASYNC16(dst, src) \
    asm volatile("cp.async.cg.shared.global [%0], [%1], 16;" :: "r"(dst), "l"(src) : "memory")
#define CP_COMMIT() asm volatile("cp.async.commit_group;" ::: "memory")

#define LDSM_X4(r0, r1, r2, r3, addr) \
    asm volatile("ldmatrix.sync.aligned.m8n8.x4.shared.b16 {%0,%1,%2,%3}, [%4];" \
        : "=r"(r0), "=r"(r1), "=r"(r2), "=r"(r3) : "r"(addr))

#define MMA16816(d, a, b0, b1) \
    asm volatile("mma.sync.aligned.m16n8k16.row.col.f32.bf16.bf16.f32 " \
        "{%0,%1,%2,%3}, {%4,%5,%6,%7}, {%8,%9}, {%0,%1,%2,%3};" \
        : "+f"((d)[0]), "+f"((d)[1]), "+f"((d)[2]), "+f"((d)[3]) \
        : "r"((a)[0]), "r"((a)[1]), "r"((a)[2]), "r"((a)[3]), "r"(b0), "r"(b1))

// ---------------- prep (single launch): z transpose+bf16+init | codebook bf16+bsq ----------------
__global__ void k_prep(const float* __restrict__ z, const float* __restrict__ cb) {
    __shared__ float tile[32][33];
    const int blk = blockIdx.x;
    const int t = threadIdx.x;

    if (blk < 4096) {
        int bx = blk & 31, by = (blk >> 5) & 7, bz = blk >> 8;
        int tx = t & 31, ty = t >> 5;
        int d0 = by * 32, p0 = bx * 32;
        const float* src = z + ((size_t)(bz * DIMD + d0) << 10) + p0;
#pragma unroll
        for (int i = ty; i < 32; i += 8)
            tile[i][tx] = src[((size_t)i << 10) + tx];

        {
            int gi = blk * 256 + t;
            if (gi < NROWS) { g_cnt[gi] = 0; g_rowmax[gi] = f2u(-1e30f); }
            if (gi == 0) { g_loss = 0.0f; g_blocks_done = 0; }
        }
        __syncthreads();

        float* dst = g_zt + (size_t)(bz * HWQ + p0) * DIMD + d0;
        __nv_bfloat16* dbf = g_zbf + (size_t)(bz * HWQ + p0) * DIMD + d0;
#pragma unroll
        for (int i = ty; i < 32; i += 8) {
            float v = tile[tx][i];
            dst[(size_t)i * DIMD + tx] = v;
            dbf[(size_t)i * DIMD + tx] = __float2bfloat16(v);
        }
    } else {
        int w = (blk - 4096) * 8 + (t >> 5);
        int lane = t & 31;
        if (w < NCODES) {
            const float4* row = reinterpret_cast<const float4*>(cb + (size_t)w * DIMD);
            float4 v0 = row[lane * 2], v1 = row[lane * 2 + 1];

            __nv_bfloat162 h0 = __floats2bfloat162_rn(v0.x, v0.y);
            __nv_bfloat162 h1 = __floats2bfloat162_rn(v0.z, v0.w);
            __nv_bfloat162 h2 = __floats2bfloat162_rn(v1.x, v1.y);
            __nv_bfloat162 h3 = __floats2bfloat162_rn(v1.z, v1.w);
            uint4 q;
            q.x = *reinterpret_cast<uint32_t*>(&h0);
            q.y = *reinterpret_cast<uint32_t*>(&h1);
            q.z = *reinterpret_cast<uint32_t*>(&h2);
            q.w = *reinterpret_cast<uint32_t*>(&h3);
            *reinterpret_cast<uint4*>(g_cbbf + (size_t)w * DIMD + lane * 8) = q;

            float s = 0.0f;
            s = fmaf(v0.x, v0.x, s); s = fmaf(v0.y, v0.y, s);
            s = fmaf(v0.z, v0.z, s); s = fmaf(v0.w, v0.w, s);
            s = fmaf(v1.x, v1.x, s); s = fmaf(v1.y, v1.y, s);
            s = fmaf(v1.z, v1.z, s); s = fmaf(v1.w, v1.w, s);
#pragma unroll
            for (int off = 16; off; off >>= 1)
                s += __shfl_xor_sync(0xFFFFFFFFu, s, off);
            if (lane == 0) g_bsq[w] = s;
        }
    }
}

// ---------------- bf16 HMMA GEMM 128x128 + fused argmax/candidate epilogue ----------------
__global__ void __launch_bounds__(256, 2) k_gemm() {
    extern __shared__ __align__(1024) unsigned char smem[];
    const uint32_t sA = smem_u32(smem);        // 2 x 16KB
    const uint32_t sB = sA + 32768;            // 2 x 16KB
    __shared__ uint32_t s_rmax[128];

    const int t = threadIdx.x;
    const int lane = t & 31, wid = t >> 5;
    const int wy = wid >> 2, wx = wid & 3;
    const int m0 = blockIdx.y * 128, n0 = blockIdx.x * 128;

    const char* gA = (const char*)(g_zbf  + (size_t)m0 * DIMD);
    const char* gB = (const char*)(g_cbbf + (size_t)n0 * DIMD);

    const int ld_row[4] = { (t + 0) >> 3, (t + 256) >> 3, (t + 512) >> 3, (t + 768) >> 3 };
    const int ld_seg = t & 7;

    float acc[4][4][4];
#pragma unroll
    for (int a = 0; a < 4; a++)
#pragma unroll
        for (int b = 0; b < 4; b++)
#pragma unroll
            for (int c = 0; c < 4; c++) acc[a][b][c] = 0.0f;

#define ISSUE(c) do {                                                           \
    uint32_t dA = sA + ((c) & 1) * 16384;                                       \
    uint32_t dB = sB + ((c) & 1) * 16384;                                       \
    _Pragma("unroll")                                                           \
    for (int i = 0; i < 4; i++) {                                               \
        uint32_t off = swz((uint32_t)(ld_row[i] * 128 + ld_seg * 16));          \
        size_t go = (size_t)ld_row[i] * 512 + (c) * 128 + ld_seg * 16;          \
        CP_ASYNC16(dA + off, gA + go);                                          \
        CP_ASYNC16(dB + off, gB + go);                                          \
    }                                                                           \
    CP_COMMIT();                                                                \
} while (0)

    ISSUE(0);
    ISSUE(1);

    const int g = lane >> 3, r = lane & 7;
    const int aRow = wy * 64 + (g & 1) * 8 + r;
    const int bRow = wx * 32 + (g & 1) * 8 + r;
    const int kCol = (g >> 1) * 8;

#pragma unroll 1
    for (int c = 0; c < 4; c++) {
        if (c < 3) asm volatile("cp.async.wait_group 1;" ::: "memory");
        else       asm volatile("cp.async.wait_group 0;" ::: "memory");
        __syncthreads();

        const uint32_t bA = sA + (c & 1) * 16384;
        const uint32_t bB = sB + (c & 1) * 16384;
#pragma unroll
        for (int ks = 0; ks < 4; ks++) {
            uint32_t af[4][4], bfr[2][4];
#pragma unroll
            for (int mt = 0; mt < 4; mt++) {
                uint32_t off = (uint32_t)((aRow + mt * 16) * 128 + (kCol + ks * 16) * 2);
                LDSM_X4(af[mt][0], af[mt][1], af[mt][2], af[mt][3], bA + swz(off));
            }
#pragma unroll
            for (int bt = 0; bt < 2; bt++) {
                uint32_t off = (uint32_t)((bRow + bt * 16) * 128 + (kCol + ks * 16) * 2);
                LDSM_X4(bfr[bt][0], bfr[bt][1], bfr[bt][2], bfr[bt][3], bB + swz(off));
            }
#pragma unroll
            for (int mt = 0; mt < 4; mt++)
#pragma unroll
                for (int bt = 0; bt < 2; bt++) {
                    MMA16816(acc[mt][bt * 2 + 0], af[mt], bfr[bt][0], bfr[bt][2]);
                    MMA16816(acc[mt][bt * 2 + 1], af[mt], bfr[bt][1], bfr[bt][3]);
                }
        }
        __syncthreads();
        if (c < 2) ISSUE(c + 2);
    }
#undef ISSUE

    // ---- fused epilogue ----
    const int cRow = lane >> 2, cCol = (lane & 3) * 2;
    float bq[8];
#pragma unroll
    for (int nn = 0; nn < 4; nn++) {
        int col = n0 + wx * 32 + nn * 8 + cCol;
        bq[nn * 2 + 0] = g_bsq[col];
        bq[nn * 2 + 1] = g_bsq[col + 1];
    }

    if (t < 128) s_rmax[t] = 0u;
    __syncthreads();

    // phase A: per-row strip max -> smem
#pragma unroll
    for (int mt = 0; mt < 4; mt++) {
#pragma unroll
        for (int h = 0; h < 2; h++) {
            float m = -1e30f;
#pragma unroll
            for (int nn = 0; nn < 4; nn++) {
                float s0 = fmaf(2.0f, acc[mt][nn][h * 2 + 0], -bq[nn * 2 + 0]);
                float s1 = fmaf(2.0f, acc[mt][nn][h * 2 + 1], -bq[nn * 2 + 1]);
                m = fmaxf(m, fmaxf(s0, s1));
            }
            atomicMax(&s_rmax[wy * 64 + mt * 16 + h * 8 + cRow], f2u(m));
        }
    }
    __syncthreads();
    // publish to global; fold the (stale-or-better) global max back into smem
    // so phase B reads thresholds from smem only. Threshold >= strip max, so
    // the push set is still a superset of the final-max filter (no false negatives).
    if (t < 128) {
        uint32_t old = atomicMax(&g_rowmax[m0 + t], s_rmax[t]);
        s_rmax[t] = max(old, s_rmax[t]);
    }
    __syncthreads();

    // phase B: push candidates (thresholds from smem)
#pragma unroll
    for (int mt = 0; mt < 4; mt++) {
#pragma unroll
        for (int h = 0; h < 2; h++) {
            int rl = wy * 64 + mt * 16 + h * 8 + cRow;
            int row = m0 + rl;
            float thr = u2f(s_rmax[rl]) - MARGIN;
#pragma unroll
            for (int nn = 0; nn < 4; nn++) {
#pragma unroll
                for (int q = 0; q < 2; q++) {
                    float s = fmaf(2.0f, acc[mt][nn][h * 2 + q], -bq[nn * 2 + q]);
                    if (s >= thr) {
                        int pos = atomicAdd(&g_cnt[row], 1);
                        if (pos < CAP)
                            g_cand[(size_t)row * CAP + pos] =
                                make_uint2((unsigned)(n0 + wx * 32 + nn * 8 + cCol + q),
                                           __float_as_uint(s));
                    }
                }
            }
        }
    }
}

// ---------------- rescue: filter by final max, exact fp32 rescore ----------------
__global__ void __launch_bounds__(256) k_rescue(const float* __restrict__ cb,
                                                float* __restrict__ out, int out_size) {
    const int w = threadIdx.x >> 5, lane = threadIdx.x & 31;
    const int row = blockIdx.x * 8 + w;

    const float thr = u2f(g_rowmax[row]) - MARGIN;
    const int cnt = g_cnt[row];

    const float4* zr = reinterpret_cast<const float4*>(g_zt + (size_t)row * DIMD);
    float4 z0 = zr[lane * 2], z1 = zr[lane * 2 + 1];
    float a = 0.0f;
    a = fmaf(z0.x, z0.x, a); a = fmaf(z0.y, z0.y, a);
    a = fmaf(z0.z, z0.z, a); a = fmaf(z0.w, z0.w, a);
    a = fmaf(z1.x, z1.x, a); a = fmaf(z1.y, z1.y, a);
    a = fmaf(z1.z, z1.z, a); a = fmaf(z1.w, z1.w, a);
#pragma unroll
    for (int off = 16; off; off >>= 1)
        a += __shfl_xor_sync(0xFFFFFFFFu, a, off);

    unsigned long long best = ~0ULL;
    if (cnt <= CAP) {
        for (int i = 0; i < cnt; i++) {
            uint2 e = g_cand[(size_t)row * CAP + i];
            if (__uint_as_float(e.y) < thr) continue;
            int k = (int)e.x;
            const float4* er = reinterpret_cast<const float4*>(cb + (size_t)k * DIMD);
            float4 e0 = er[lane * 2], e1 = er[lane * 2 + 1];
            float dot = 0.0f;
            dot = fmaf(z0.x, e0.x, dot); dot = fmaf(z0.y, e0.y, dot);
            dot = fmaf(z0.z, e0.z, dot); dot = fmaf(z0.w, e0.w, dot);
            dot = fmaf(z1.x, e1.x, dot); dot = fmaf(z1.y, e1.y, dot);
            dot = fmaf(z1.z, e1.z, dot); dot = fmaf(z1.w, e1.w, dot);
#pragma unroll
            for (int off = 16; off; off >>= 1)
                dot += __shfl_xor_sync(0xFFFFFFFFu, dot, off);
            float dist = __fadd_rn(__fadd_rn(a, g_bsq[k]), -2.0f * dot);
            unsigned long long key = ((unsigned long long)__float_as_uint(dist) << 32) | (unsigned)k;
            if (key < best) best = key;
        }
    } else {
        for (int k = 0; k < NCODES; k++) {
            const float4* er = reinterpret_cast<const float4*>(cb + (size_t)k * DIMD);
            float4 e0 = er[lane * 2], e1 = er[lane * 2 + 1];
            float dot = 0.0f;
            dot = fmaf(z0.x, e0.x, dot); dot = fmaf(z0.y, e0.y, dot);
            dot = fmaf(z0.z, e0.z, dot); dot = fmaf(z0.w, e0.w, dot);
            dot = fmaf(z1.x, e1.x, dot); dot = fmaf(z1.y, e1.y, dot);
            dot = fmaf(z1.z, e1.z, dot); dot = fmaf(z1.w, e1.w, dot);
#pragma unroll
            for (int off = 16; off; off >>= 1)
                dot += __shfl_xor_sync(0xFFFFFFFFu, dot, off);
            float dist = __fadd_rn(__fadd_rn(a, g_bsq[k]), -2.0f * dot);
            unsigned long long key = ((unsigned long long)__float_as_uint(dist) << 32) | (unsigned)k;
            if (key < best) best = key;
        }
    }
    if (lane == 0) {
        int idx = (int)(best & 0xFFFFFFFFu);
        g_idx[row] = idx;
        if (out_size >= ZQ_ELEMS + NROWS) out[ZQ_ELEMS + row] = (float)idx;
    }
}

// ---------------- output + fused loss: smem-transposed, fully coalesced ----------------
__global__ void __launch_bounds__(256) k_output(const float* __restrict__ cb,
                                                float* __restrict__ out, int out_size) {
    __shared__ float tile[256][33];
    __shared__ float warpsum[8];

    const int t = threadIdx.x, lane = t & 31, w = t >> 5;
    const int n0 = blockIdx.x * 32;
    const int b = n0 >> 10, p0 = n0 & 1023;

    float dsq = 0.0f;
#pragma unroll
    for (int it = 0; it < 4; it++) {
        int pl = it * 8 + w;
        int n = n0 + pl;
        int idx = g_idx[n];
        const float* er = cb   + (size_t)idx * DIMD;
        const float* zr = g_zt + (size_t)n   * DIMD;
#pragma unroll
        for (int j = 0; j < 8; j++) {
            int d = lane + 32 * j;
            float zv = zr[d];
            float e  = er[d];
            float f  = __fadd_rn(e, -zv);
            tile[d][pl] = __fadd_rn(zv, f);
            dsq = fmaf(f, f, dsq);
        }
    }
    __syncthreads();

    const int dr = t >> 3, pq = (t & 7) * 4;
#pragma unroll
    for (int g8 = 0; g8 < 8; g8++) {
        int d = g8 * 32 + dr;
        float4 o;
        o.x = tile[d][pq + 0];
        o.y = tile[d][pq + 1];
        o.z = tile[d][pq + 2];
        o.w = tile[d][pq + 3];
        size_t i = (size_t)b * DIMD * HWQ + (size_t)d * HWQ + p0 + pq;
        if (i + 3 < (size_t)out_size) {
            *reinterpret_cast<float4*>(out + i) = o;
        } else {
            if (i + 0 < (size_t)out_size) out[i + 0] = o.x;
            if (i + 1 < (size_t)out_size) out[i + 1] = o.y;
            if (i + 2 < (size_t)out_size) out[i + 2] = o.z;
            if (i + 3 < (size_t)out_size) out[i + 3] = o.w;
        }
    }

#pragma unroll
    for (int off = 16; off; off >>= 1)
        dsq += __shfl_xor_sync(0xFFFFFFFFu, dsq, off);
    if (lane == 0) warpsum[w] = dsq;
    __syncthreads();
    if (t == 0) {
        float s = 0.0f;
#pragma unroll
        for (int q = 0; q < 8; q++) s += warpsum[q];
        atomicAdd(&g_loss, s);
        __threadfence();
        int done = atomicAdd(&g_blocks_done, 1);
        if (done == (int)gridDim.x - 1) {
            g_blocks_done = 0;
            if (out_size >= ZQ_ELEMS + NROWS + 1) {
                float mean = g_loss / (float)ZQ_ELEMS;
                out[ZQ_ELEMS + NROWS] = 0.25f * mean;
            }
        }
    }
}

extern "C" void kernel_launch(void* const* d_in, const int* in_sizes, int n_in,
                              void* d_out, int out_size) {
    const float* z;
    const float* cb;
    if (n_in >= 2 && in_sizes[0] == ZQ_ELEMS) {
        z = (const float*)d_in[0]; cb = (const float*)d_in[1];
    } else {
        z = (const float*)d_in[1]; cb = (const float*)d_in[0];
    }
    float* out = (float*)d_out;

    cudaFuncSetAttribute(k_gemm, cudaFuncAttributeMaxDynamicSharedMemorySize, 65536);

    k_prep<<<4096 + NCODES / 8, 256>>>(z, cb);

    dim3 grid(NCODES / 128, NROWS / 128);  // (64, 128)
    k_gemm<<<grid, 256, 65536>>>();

    k_rescue<<<NROWS / 8, 256>>>(cb, out, out_size);
    k_output<<<NROWS / 32, 256>>>(cb, out, out_size);
}

// round 14
// speedup vs baseline: 1.9165x; 1.0005x over previous
#include <cuda_runtime.h>
#include <cuda_bf16.h>
#include <cstdint>

#define NROWS    16384
#define NCODES   8192
#define DIMD     256
#define HWQ      1024
#define ZQ_ELEMS 4194304
#define MARGIN   2e-4f
#define CAP      512

// Scratch (device globals; no allocations allowed)
__device__ __align__(16) __nv_bfloat16 g_zbf[NROWS * DIMD];    // 8 MB
__device__ __align__(16) __nv_bfloat16 g_cbbf[NCODES * DIMD];  // 4 MB
__device__ __align__(16) float         g_zt[NROWS * DIMD];     // 16 MB exact fp32
__device__ float g_bsq[NCODES];
__device__ uint32_t g_rowmax[NROWS];
__device__ int      g_cnt[NROWS];
__device__ __align__(16) uint2 g_cand[(size_t)NROWS * CAP];    // 64 MB
__device__ float g_loss;
__device__ int   g_blocks_done;

// ---------------- helpers ----------------
__device__ __forceinline__ uint32_t smem_u32(const void* p) {
    uint32_t a;
    asm("{ .reg .u64 t; cvta.to.shared.u64 t, %1; cvt.u32.u64 %0, t; }" : "=r"(a) : "l"(p));
    return a;
}
__device__ __forceinline__ uint32_t swz(uint32_t off) { return off ^ ((off >> 3) & 0x70); }
__device__ __forceinline__ uint32_t f2u(float f) {
    uint32_t b = __float_as_uint(f);
    return (b >> 31) ? ~b : (b | 0x80000000u);
}
__device__ __forceinline__ float u2f(uint32_t u) {
    return __uint_as_float((u >> 31) ? (u & 0x7FFFFFFFu) : ~u);
}

#define CP_ASYNC16(dst, src) \
    asm volatile("cp.async.cg.shared.global [%0], [%1], 16;" :: "r"(dst), "l"(src) : "memory")
#define CP_COMMIT() asm volatile("cp.async.commit_group;" ::: "memory")

#define LDSM_X4(r0, r1, r2, r3, addr) \
    asm volatile("ldmatrix.sync.aligned.m8n8.x4.shared.b16 {%0,%1,%2,%3}, [%4];" \
        : "=r"(r0), "=r"(r1), "=r"(r2), "=r"(r3) : "r"(addr))

#define MMA16816(d, a, b0, b1) \
    asm volatile("mma.sync.aligned.m16n8k16.row.col.f32.bf16.bf16.f32 " \
        "{%0,%1,%2,%3}, {%4,%5,%6,%7}, {%8,%9}, {%0,%1,%2,%3};" \
        : "+f"((d)[0]), "+f"((d)[1]), "+f"((d)[2]), "+f"((d)[3]) \
        : "r"((a)[0]), "r"((a)[1]), "r"((a)[2]), "r"((a)[3]), "r"(b0), "r"(b1))

// ---------------- prep (single launch): z transpose+bf16+init | codebook bf16+bsq ----------------
__global__ void k_prep(const float* __restrict__ z, const float* __restrict__ cb) {
    __shared__ float tile[32][33];
    const int blk = blockIdx.x;
    const int t = threadIdx.x;

    if (blk < 4096) {
        int bx = blk & 31, by = (blk >> 5) & 7, bz = blk >> 8;
        int tx = t & 31, ty = t >> 5;
        int d0 = by * 32, p0 = bx * 32;
        const float* src = z + ((size_t)(bz * DIMD + d0) << 10) + p0;
#pragma unroll
        for (int i = ty; i < 32; i += 8)
            tile[i][tx] = src[((size_t)i << 10) + tx];

        {
            int gi = blk * 256 + t;
            if (gi < NROWS) { g_cnt[gi] = 0; g_rowmax[gi] = f2u(-1e30f); }
            if (gi == 0) { g_loss = 0.0f; g_blocks_done = 0; }
        }
        __syncthreads();

        float* dst = g_zt + (size_t)(bz * HWQ + p0) * DIMD + d0;
        __nv_bfloat16* dbf = g_zbf + (size_t)(bz * HWQ + p0) * DIMD + d0;
#pragma unroll
        for (int i = ty; i < 32; i += 8) {
            float v = tile[tx][i];
            dst[(size_t)i * DIMD + tx] = v;
            dbf[(size_t)i * DIMD + tx] = __float2bfloat16(v);
        }
    } else {
        int w = (blk - 4096) * 8 + (t >> 5);
        int lane = t & 31;
        if (w < NCODES) {
            const float4* row = reinterpret_cast<const float4*>(cb + (size_t)w * DIMD);
            float4 v0 = row[lane * 2], v1 = row[lane * 2 + 1];

            __nv_bfloat162 h0 = __floats2bfloat162_rn(v0.x, v0.y);
            __nv_bfloat162 h1 = __floats2bfloat162_rn(v0.z, v0.w);
            __nv_bfloat162 h2 = __floats2bfloat162_rn(v1.x, v1.y);
            __nv_bfloat162 h3 = __floats2bfloat162_rn(v1.z, v1.w);
            uint4 q;
            q.x = *reinterpret_cast<uint32_t*>(&h0);
            q.y = *reinterpret_cast<uint32_t*>(&h1);
            q.z = *reinterpret_cast<uint32_t*>(&h2);
            q.w = *reinterpret_cast<uint32_t*>(&h3);
            *reinterpret_cast<uint4*>(g_cbbf + (size_t)w * DIMD + lane * 8) = q;

            float s = 0.0f;
            s = fmaf(v0.x, v0.x, s); s = fmaf(v0.y, v0.y, s);
            s = fmaf(v0.z, v0.z, s); s = fmaf(v0.w, v0.w, s);
            s = fmaf(v1.x, v1.x, s); s = fmaf(v1.y, v1.y, s);
            s = fmaf(v1.z, v1.z, s); s = fmaf(v1.w, v1.w, s);
#pragma unroll
            for (int off = 16; off; off >>= 1)
                s += __shfl_xor_sync(0xFFFFFFFFu, s, off);
            if (lane == 0) g_bsq[w] = s;
        }
    }
}

// ---------------- bf16 HMMA GEMM 128x128 + fused argmax/candidate epilogue ----------------
__global__ void __launch_bounds__(256, 2) k_gemm() {
    extern __shared__ __align__(1024) unsigned char smem[];
    const uint32_t sA = smem_u32(smem);        // 2 x 16KB
    const uint32_t sB = sA + 32768;            // 2 x 16KB
    __shared__ uint32_t s_rmax[128];

    const int t = threadIdx.x;
    const int lane = t & 31, wid = t >> 5;
    const int wy = wid >> 2, wx = wid & 3;
    const int m0 = blockIdx.y * 128, n0 = blockIdx.x * 128;

    const char* gA = (const char*)(g_zbf  + (size_t)m0 * DIMD);
    const char* gB = (const char*)(g_cbbf + (size_t)n0 * DIMD);

    const int ld_row[4] = { (t + 0) >> 3, (t + 256) >> 3, (t + 512) >> 3, (t + 768) >> 3 };
    const int ld_seg = t & 7;

    float acc[4][4][4];
#pragma unroll
    for (int a = 0; a < 4; a++)
#pragma unroll
        for (int b = 0; b < 4; b++)
#pragma unroll
            for (int c = 0; c < 4; c++) acc[a][b][c] = 0.0f;

#define ISSUE(c) do {                                                           \
    uint32_t dA = sA + ((c) & 1) * 16384;                                       \
    uint32_t dB = sB + ((c) & 1) * 16384;                                       \
    _Pragma("unroll")                                                           \
    for (int i = 0; i < 4; i++) {                                               \
        uint32_t off = swz((uint32_t)(ld_row[i] * 128 + ld_seg * 16));          \
        size_t go = (size_t)ld_row[i] * 512 + (c) * 128 + ld_seg * 16;          \
        CP_ASYNC16(dA + off, gA + go);                                          \
        CP_ASYNC16(dB + off, gB + go);                                          \
    }                                                                           \
    CP_COMMIT();                                                                \
} while (0)

    ISSUE(0);
    ISSUE(1);

    const int g = lane >> 3, r = lane & 7;
    const int aRow = wy * 64 + (g & 1) * 8 + r;
    const int bRow = wx * 32 + (g & 1) * 8 + r;
    const int kCol = (g >> 1) * 8;

#pragma unroll 1
    for (int c = 0; c < 4; c++) {
        if (c < 3) asm volatile("cp.async.wait_group 1;" ::: "memory");
        else       asm volatile("cp.async.wait_group 0;" ::: "memory");
        __syncthreads();

        const uint32_t bA = sA + (c & 1) * 16384;
        const uint32_t bB = sB + (c & 1) * 16384;
#pragma unroll
        for (int ks = 0; ks < 4; ks++) {
            uint32_t af[4][4], bfr[2][4];
#pragma unroll
            for (int mt = 0; mt < 4; mt++) {
                uint32_t off = (uint32_t)((aRow + mt * 16) * 128 + (kCol + ks * 16) * 2);
                LDSM_X4(af[mt][0], af[mt][1], af[mt][2], af[mt][3], bA + swz(off));
            }
#pragma unroll
            for (int bt = 0; bt < 2; bt++) {
                uint32_t off = (uint32_t)((bRow + bt * 16) * 128 + (kCol + ks * 16) * 2);
                LDSM_X4(bfr[bt][0], bfr[bt][1], bfr[bt][2], bfr[bt][3], bB + swz(off));
            }
#pragma unroll
            for (int mt = 0; mt < 4; mt++)
#pragma unroll
                for (int bt = 0; bt < 2; bt++) {
                    MMA16816(acc[mt][bt * 2 + 0], af[mt], bfr[bt][0], bfr[bt][2]);
                    MMA16816(acc[mt][bt * 2 + 1], af[mt], bfr[bt][1], bfr[bt][3]);
                }
        }
        __syncthreads();
        if (c < 2) ISSUE(c + 2);
    }
#undef ISSUE

    // ---- fused epilogue ----
    const int cRow = lane >> 2, cCol = (lane & 3) * 2;
    float bq[8];
#pragma unroll
    for (int nn = 0; nn < 4; nn++) {
        int col = n0 + wx * 32 + nn * 8 + cCol;
        bq[nn * 2 + 0] = g_bsq[col];
        bq[nn * 2 + 1] = g_bsq[col + 1];
    }

    if (t < 128) s_rmax[t] = 0u;
    __syncthreads();

    // phase A: per-row strip max -> smem
#pragma unroll
    for (int mt = 0; mt < 4; mt++) {
#pragma unroll
        for (int h = 0; h < 2; h++) {
            float m = -1e30f;
#pragma unroll
            for (int nn = 0; nn < 4; nn++) {
                float s0 = fmaf(2.0f, acc[mt][nn][h * 2 + 0], -bq[nn * 2 + 0]);
                float s1 = fmaf(2.0f, acc[mt][nn][h * 2 + 1], -bq[nn * 2 + 1]);
                m = fmaxf(m, fmaxf(s0, s1));
            }
            atomicMax(&s_rmax[wy * 64 + mt * 16 + h * 8 + cRow], f2u(m));
        }
    }
    __syncthreads();
    // publish to global; fold the (stale-or-better) global max back into smem.
    if (t < 128) {
        uint32_t old = atomicMax(&g_rowmax[m0 + t], s_rmax[t]);
        s_rmax[t] = max(old, s_rmax[t]);
    }
    __syncthreads();

    // phase B: push candidates (thresholds from smem; superset of final-max filter)
#pragma unroll
    for (int mt = 0; mt < 4; mt++) {
#pragma unroll
        for (int h = 0; h < 2; h++) {
            int rl = wy * 64 + mt * 16 + h * 8 + cRow;
            int row = m0 + rl;
            float thr = u2f(s_rmax[rl]) - MARGIN;
#pragma unroll
            for (int nn = 0; nn < 4; nn++) {
#pragma unroll
                for (int q = 0; q < 2; q++) {
                    float s = fmaf(2.0f, acc[mt][nn][h * 2 + q], -bq[nn * 2 + q]);
                    if (s >= thr) {
                        int pos = atomicAdd(&g_cnt[row], 1);
                        if (pos < CAP)
                            g_cand[(size_t)row * CAP + pos] =
                                make_uint2((unsigned)(n0 + wx * 32 + nn * 8 + cCol + q),
                                           __float_as_uint(s));
                    }
                }
            }
        }
    }
}

// ---------------- finish: rescue (exact fp32 rescore) + z_q_st output + loss, fused ----------------
// One block per 32 consecutive rows. Phase 1: warp w rescues rows n0 + it*8 + w
// (it = 0..3), index -> smem + indices output. Phase 2: smem-transposed coalesced
// z_q_st writeback + loss (completion counter writes final loss).
__global__ void __launch_bounds__(256) k_finish(const float* __restrict__ cb,
                                                float* __restrict__ out, int out_size) {
    __shared__ float tile[256][33];
    __shared__ int   s_idx[32];
    __shared__ float warpsum[8];

    const int t = threadIdx.x, lane = t & 31, w = t >> 5;
    const int n0 = blockIdx.x * 32;
    const int b = n0 >> 10, p0 = n0 & 1023;

    // ---- phase 1: rescue (bit-identical arithmetic to the passing R13 k_rescue) ----
#pragma unroll 1
    for (int it = 0; it < 4; it++) {
        const int pl = it * 8 + w;
        const int row = n0 + pl;

        const float thr = u2f(g_rowmax[row]) - MARGIN;
        const int cnt = g_cnt[row];

        const float4* zr = reinterpret_cast<const float4*>(g_zt + (size_t)row * DIMD);
        float4 z0 = zr[lane * 2], z1 = zr[lane * 2 + 1];
        float a = 0.0f;
        a = fmaf(z0.x, z0.x, a); a = fmaf(z0.y, z0.y, a);
        a = fmaf(z0.z, z0.z, a); a = fmaf(z0.w, z0.w, a);
        a = fmaf(z1.x, z1.x, a); a = fmaf(z1.y, z1.y, a);
        a = fmaf(z1.z, z1.z, a); a = fmaf(z1.w, z1.w, a);
#pragma unroll
        for (int off = 16; off; off >>= 1)
            a += __shfl_xor_sync(0xFFFFFFFFu, a, off);

        unsigned long long best = ~0ULL;
        if (cnt <= CAP) {
            for (int i = 0; i < cnt; i++) {
                uint2 e = g_cand[(size_t)row * CAP + i];
                if (__uint_as_float(e.y) < thr) continue;
                int k = (int)e.x;
                const float4* er = reinterpret_cast<const float4*>(cb + (size_t)k * DIMD);
                float4 e0 = er[lane * 2], e1 = er[lane * 2 + 1];
                float dot = 0.0f;
                dot = fmaf(z0.x, e0.x, dot); dot = fmaf(z0.y, e0.y, dot);
                dot = fmaf(z0.z, e0.z, dot); dot = fmaf(z0.w, e0.w, dot);
                dot = fmaf(z1.x, e1.x, dot); dot = fmaf(z1.y, e1.y, dot);
                dot = fmaf(z1.z, e1.z, dot); dot = fmaf(z1.w, e1.w, dot);
#pragma unroll
                for (int off = 16; off; off >>= 1)
                    dot += __shfl_xor_sync(0xFFFFFFFFu, dot, off);
                float dist = __fadd_rn(__fadd_rn(a, g_bsq[k]), -2.0f * dot);
                unsigned long long key = ((unsigned long long)__float_as_uint(dist) << 32) | (unsigned)k;
                if (key < best) best = key;
            }
        } else {
            for (int k = 0; k < NCODES; k++) {
                const float4* er = reinterpret_cast<const float4*>(cb + (size_t)k * DIMD);
                float4 e0 = er[lane * 2], e1 = er[lane * 2 + 1];
                float dot = 0.0f;
                dot = fmaf(z0.x, e0.x, dot); dot = fmaf(z0.y, e0.y, dot);
                dot = fmaf(z0.z, e0.z, dot); dot = fmaf(z0.w, e0.w, dot);
                dot = fmaf(z1.x, e1.x, dot); dot = fmaf(z1.y, e1.y, dot);
                dot = fmaf(z1.z, e1.z, dot); dot = fmaf(z1.w, e1.w, dot);
#pragma unroll
                for (int off = 16; off; off >>= 1)
                    dot += __shfl_xor_sync(0xFFFFFFFFu, dot, off);
                float dist = __fadd_rn(__fadd_rn(a, g_bsq[k]), -2.0f * dot);
                unsigned long long key = ((unsigned long long)__float_as_uint(dist) << 32) | (unsigned)k;
                if (key < best) best = key;
            }
        }
        if (lane == 0) {
            int idx = (int)(best & 0xFFFFFFFFu);
            s_idx[pl] = idx;
            if (out_size >= ZQ_ELEMS + NROWS) out[ZQ_ELEMS + row] = (float)idx;
        }
    }
    __syncthreads();

    // ---- phase 2: z_q_st output (smem transpose, coalesced) + loss ----
    float dsq = 0.0f;
#pragma unroll
    for (int it = 0; it < 4; it++) {
        int pl = it * 8 + w;
        int n = n0 + pl;
        int idx = s_idx[pl];
        const float* er = cb   + (size_t)idx * DIMD;
        const float* zr = g_zt + (size_t)n   * DIMD;
#pragma unroll
        for (int j = 0; j < 8; j++) {
            int d = lane + 32 * j;
            float zv = zr[d];
            float e  = er[d];
            float f  = __fadd_rn(e, -zv);
            tile[d][pl] = __fadd_rn(zv, f);
            dsq = fmaf(f, f, dsq);
        }
    }
    __syncthreads();

    const int dr = t >> 3, pq = (t & 7) * 4;
#pragma unroll
    for (int g8 = 0; g8 < 8; g8++) {
        int d = g8 * 32 + dr;
        float4 o;
        o.x = tile[d][pq + 0];
        o.y = tile[d][pq + 1];
        o.z = tile[d][pq + 2];
        o.w = tile[d][pq + 3];
        size_t i = (size_t)b * DIMD * HWQ + (size_t)d * HWQ + p0 + pq;
        if (i + 3 < (size_t)out_size) {
            *reinterpret_cast<float4*>(out + i) = o;
        } else {
            if (i + 0 < (size_t)out_size) out[i + 0] = o.x;
            if (i + 1 < (size_t)out_size) out[i + 1] = o.y;
            if (i + 2 < (size_t)out_size) out[i + 2] = o.z;
            if (i + 3 < (size_t)out_size) out[i + 3] = o.w;
        }
    }

#pragma unroll
    for (int off = 16; off; off >>= 1)
        dsq += __shfl_xor_sync(0xFFFFFFFFu, dsq, off);
    if (lane == 0) warpsum[w] = dsq;
    __syncthreads();
    if (t == 0) {
        float s = 0.0f;
#pragma unroll
        for (int q = 0; q < 8; q++) s += warpsum[q];
        atomicAdd(&g_loss, s);
        __threadfence();
        int done = atomicAdd(&g_blocks_done, 1);
        if (done == (int)gridDim.x - 1) {
            g_blocks_done = 0;
            if (out_size >= ZQ_ELEMS + NROWS + 1) {
                float mean = g_loss / (float)ZQ_ELEMS;
                out[ZQ_ELEMS + NROWS] = 0.25f * mean;
            }
        }
    }
}

extern "C" void kernel_launch(void* const* d_in, const int* in_sizes, int n_in,
                              void* d_out, int out_size) {
    const float* z;
    const float* cb;
    if (n_in >= 2 && in_sizes[0] == ZQ_ELEMS) {
        z = (const float*)d_in[0]; cb = (const float*)d_in[1];
    } else {
        z = (const float*)d_in[1]; cb = (const float*)d_in[0];
    }
    float* out = (float*)d_out;

    cudaFuncSetAttribute(k_gemm, cudaFuncAttributeMaxDynamicSharedMemorySize, 65536);

    k_prep<<<4096 + NCODES / 8, 256>>>(z, cb);

    dim3 grid(NCODES / 128, NROWS / 128);  // (64, 128)
    k_gemm<<<grid, 256, 65536>>>();

    k_finish<<<NROWS / 32, 256>>>(cb, out, out_size);
}